// round 1
// baseline (speedup 1.0000x reference)
#include <cuda_runtime.h>

#define NO_MAX 100000
#define NR_MAX 1000
#define E_MAX  1000000

// ---------------- scratch (device globals; no allocations) ----------------
__device__ float g_A[NR_MAX * 64];      // Wk @ q_r
__device__ float g_c1[NR_MAX];          // q_r . bk
__device__ float g_qWe[NR_MAX * 4];     // We @ q_r
__device__ float g_rskip[NR_MAX * 64];  // x_rider@Wskip + bskip
__device__ float g_Wc[64 * 128];        // Wp @ W1[0:64]
__device__ float g_cvec[128];           // omega@W1c + b1 + bp@W1a
__device__ int   g_counts[NR_MAX];
__device__ int   g_starts[NR_MAX];
__device__ int   g_cursor[NR_MAX];
__device__ int   g_perm[E_MAX];
__device__ float g_O[(long long)NO_MAX * 128];  // 51.2 MB, L2-resident
__device__ float g_R[NR_MAX * 128];     // rider_emb @ W1b
__device__ float g_Wpre[NR_MAX * 64];   // Wp @ rider_emb
__device__ float g_c2[NR_MAX];          // bp . rider_emb

// ---------------- per-rider precompute ----------------
__global__ void k_rider_pre(const float* __restrict__ xr,
                            const float* __restrict__ Wq, const float* __restrict__ bq,
                            const float* __restrict__ Wk, const float* __restrict__ bk,
                            const float* __restrict__ We,
                            const float* __restrict__ Wsk, const float* __restrict__ bsk) {
    int r = blockIdx.x, h = threadIdx.x;  // 64 threads
    __shared__ float xs[32], qs[64];
    if (h < 32) xs[h] = xr[r * 32 + h];
    __syncthreads();
    float q = bq[h];
#pragma unroll 8
    for (int d = 0; d < 32; d++) q += xs[d] * Wq[d * 64 + h];
    qs[h] = q;
    float sk = bsk[h];
#pragma unroll 8
    for (int d = 0; d < 32; d++) sk += xs[d] * Wsk[d * 64 + h];
    g_rskip[r * 64 + h] = sk;
    __syncthreads();
    float a = 0.f;
#pragma unroll 8
    for (int t = 0; t < 64; t++) a += Wk[h * 64 + t] * qs[t];
    g_A[r * 64 + h] = a;
    if (h < 4) {
        float w = 0.f;
        for (int t = 0; t < 64; t++) w += We[h * 64 + t] * qs[t];
        g_qWe[r * 4 + h] = w;
    }
    if (h == 0) {
        float c = 0.f;
        for (int t = 0; t < 64; t++) c += bk[t] * qs[t];
        g_c1[r] = c;
    }
}

__global__ void k_const(const float* __restrict__ omg, const float* __restrict__ W1,
                        const float* __restrict__ b1, const float* __restrict__ bp) {
    int j = threadIdx.x;  // 128
    float c = b1[j];
    for (int m = 0; m < 32; m++) c += omg[m] * W1[(128 + m) * 128 + j];
    for (int d = 0; d < 64; d++) c += bp[d] * W1[d * 128 + j];
    g_cvec[j] = c;
}

__global__ void k_wc(const float* __restrict__ Wp, const float* __restrict__ W1) {
    __shared__ float wp[64];
    int d = blockIdx.x, j = threadIdx.x;  // 64 blocks x 128 threads
    if (j < 64) wp[j] = Wp[d * 64 + j];
    __syncthreads();
    float acc = 0.f;
#pragma unroll 8
    for (int t = 0; t < 64; t++) acc += wp[t] * W1[t * 128 + j];
    g_Wc[d * 128 + j] = acc;
}

// ---------------- bucket edges by rider (counting sort) ----------------
__global__ void k_zero(int NRv) {
    int t = threadIdx.x;
    if (t < NRv) g_counts[t] = 0;
}

__global__ void k_hist(const int* __restrict__ ridx, int E, int NRv) {
    __shared__ int sh[NR_MAX];
    int tid = threadIdx.x;
    for (int i = tid; i < NRv; i += blockDim.x) sh[i] = 0;
    __syncthreads();
    for (int e = blockIdx.x * blockDim.x + tid; e < E; e += gridDim.x * blockDim.x)
        atomicAdd(&sh[ridx[e]], 1);
    __syncthreads();
    for (int i = tid; i < NRv; i += blockDim.x) {
        int c = sh[i];
        if (c) atomicAdd(&g_counts[i], c);
    }
}

__global__ void k_scan(int NRv) {
    __shared__ int s[1024];
    int t = threadIdx.x;
    int v = (t < NRv) ? g_counts[t] : 0;
    s[t] = v;
    __syncthreads();
    for (int off = 1; off < 1024; off <<= 1) {
        int u = (t >= off) ? s[t - off] : 0;
        __syncthreads();
        s[t] += u;
        __syncthreads();
    }
    if (t < NRv) {
        int st = s[t] - v;
        g_starts[t] = st;
        g_cursor[t] = st;
    }
}

__global__ void k_scatter(const int* __restrict__ ridx, int E) {
    for (int e = blockIdx.x * blockDim.x + threadIdx.x; e < E; e += gridDim.x * blockDim.x) {
        int r = ridx[e];
        int pos = atomicAdd(&g_cursor[r], 1);
        g_perm[pos] = e;
    }
}

// ---------------- O = x_order @ Wc  (NOx64 @ 64x128, 128x128 tiles) ----------------
__global__ void __launch_bounds__(256) k_O(const float* __restrict__ xo, int NOv) {
    extern __shared__ float dsm[];
    float* Xs  = dsm;             // [128][68]
    float* Wcs = dsm + 128 * 68;  // [64][128]
    int tx = threadIdx.x, ty = threadIdx.y;  // 16x16
    int tid = ty * 16 + tx;
    int row0 = blockIdx.x * 128;
    for (int i = tid; i < 64 * 32; i += 256)
        ((float4*)Wcs)[i] = ((const float4*)g_Wc)[i];
    for (int i = tid; i < 128 * 16; i += 256) {
        int row = i >> 4, kq = i & 15;
        float4 xv = make_float4(0.f, 0.f, 0.f, 0.f);
        int gr = row0 + row;
        if (gr < NOv) xv = ((const float4*)xo)[gr * 16 + kq];
        *((float4*)(Xs + row * 68 + kq * 4)) = xv;
    }
    __syncthreads();
    float acc[8][8];
#pragma unroll
    for (int i = 0; i < 8; i++)
#pragma unroll
        for (int j = 0; j < 8; j++) acc[i][j] = 0.f;
#pragma unroll 8
    for (int k = 0; k < 64; k++) {
        float a[8];
#pragma unroll
        for (int i = 0; i < 8; i++) a[i] = Xs[(ty * 8 + i) * 68 + k];
        float4 b0 = *((const float4*)(Wcs + k * 128 + tx * 4));
        float4 b1 = *((const float4*)(Wcs + k * 128 + 64 + tx * 4));
#pragma unroll
        for (int i = 0; i < 8; i++) {
            acc[i][0] += a[i] * b0.x; acc[i][1] += a[i] * b0.y;
            acc[i][2] += a[i] * b0.z; acc[i][3] += a[i] * b0.w;
            acc[i][4] += a[i] * b1.x; acc[i][5] += a[i] * b1.y;
            acc[i][6] += a[i] * b1.z; acc[i][7] += a[i] * b1.w;
        }
    }
#pragma unroll
    for (int i = 0; i < 8; i++) {
        int gr = row0 + ty * 8 + i;
        if (gr < NOv) {
            ((float4*)g_O)[(long long)gr * 32 + tx] =
                make_float4(acc[i][0], acc[i][1], acc[i][2], acc[i][3]);
            ((float4*)g_O)[(long long)gr * 32 + 16 + tx] =
                make_float4(acc[i][4], acc[i][5], acc[i][6], acc[i][7]);
        }
    }
}

// ---------------- attention: one CTA per rider, single pass ----------------
__global__ void __launch_bounds__(128) k_att(
    const float* __restrict__ xo, const float* __restrict__ eat,
    const int* __restrict__ oidx,
    const float* __restrict__ Wv, const float* __restrict__ bv,
    const float* __restrict__ We, const float* __restrict__ Wp,
    const float* __restrict__ bp, const float* __restrict__ W1) {
    int r = blockIdx.x, tid = threadIdx.x;
    int lane = tid & 31, warp = tid >> 5;
    __shared__ float As[64], qWes[4], c1s;
    __shared__ float wsum[4][64];
    __shared__ float wsc[4][8];
    __shared__ float xs_s[64], remb_s[64], eas[4], asum_s;
    if (tid < 64) As[tid] = g_A[r * 64 + tid];
    if (tid < 4)  qWes[tid] = g_qWe[r * 4 + tid];
    if (tid == 0) c1s = g_c1[r];
    __syncthreads();
    int start = g_starts[r], cnt = g_counts[r];
    float xsum[64];
#pragma unroll
    for (int d = 0; d < 64; d++) xsum[d] = 0.f;
    float asum = 0.f, e0 = 0.f, e1 = 0.f, e2 = 0.f, e3 = 0.f;
    for (int i = tid; i < cnt; i += 128) {
        int e = g_perm[start + i];
        int o = oidx[e];
        float4 ea = __ldg((const float4*)eat + e);
        const float4* xp = (const float4*)(xo + (long long)o * 64);
        float4 xv[16];
        float dot = c1s + ea.x * qWes[0] + ea.y * qWes[1] + ea.z * qWes[2] + ea.w * qWes[3];
#pragma unroll
        for (int q = 0; q < 16; q++) {
            xv[q] = __ldg(xp + q);
            dot += xv[q].x * As[4 * q] + xv[q].y * As[4 * q + 1] +
                   xv[q].z * As[4 * q + 2] + xv[q].w * As[4 * q + 3];
        }
        float w = __expf(0.125f * dot);  // softmax shift-invariance: no max needed
        asum += w;
        e0 += w * ea.x; e1 += w * ea.y; e2 += w * ea.z; e3 += w * ea.w;
#pragma unroll
        for (int q = 0; q < 16; q++) {
            xsum[4 * q]     += w * xv[q].x;
            xsum[4 * q + 1] += w * xv[q].y;
            xsum[4 * q + 2] += w * xv[q].z;
            xsum[4 * q + 3] += w * xv[q].w;
        }
    }
    // reduce 64-vector + 5 scalars across the CTA
#pragma unroll
    for (int d = 0; d < 64; d++) {
        float v = xsum[d];
        v += __shfl_xor_sync(0xffffffffu, v, 16);
        v += __shfl_xor_sync(0xffffffffu, v, 8);
        v += __shfl_xor_sync(0xffffffffu, v, 4);
        v += __shfl_xor_sync(0xffffffffu, v, 2);
        v += __shfl_xor_sync(0xffffffffu, v, 1);
        if (lane == 0) wsum[warp][d] = v;
    }
    float sc[5] = {asum, e0, e1, e2, e3};
#pragma unroll
    for (int j = 0; j < 5; j++) {
        float v = sc[j];
        v += __shfl_xor_sync(0xffffffffu, v, 16);
        v += __shfl_xor_sync(0xffffffffu, v, 8);
        v += __shfl_xor_sync(0xffffffffu, v, 4);
        v += __shfl_xor_sync(0xffffffffu, v, 2);
        v += __shfl_xor_sync(0xffffffffu, v, 1);
        if (lane == 0) wsc[warp][j] = v;
    }
    __syncthreads();
    if (tid < 64) xs_s[tid] = wsum[0][tid] + wsum[1][tid] + wsum[2][tid] + wsum[3][tid];
    if (tid < 5) {
        float v = wsc[0][tid] + wsc[1][tid] + wsc[2][tid] + wsc[3][tid];
        if (tid == 0) asum_s = v; else eas[tid - 1] = v;
    }
    __syncthreads();
    if (tid < 64) {
        int h = tid;
        float t = asum_s * bv[h];
#pragma unroll 8
        for (int d = 0; d < 64; d++) t += xs_s[d] * Wv[d * 64 + h];
        t += eas[0] * We[h] + eas[1] * We[64 + h] + eas[2] * We[128 + h] + eas[3] * We[192 + h];
        remb_s[h] = t / (asum_s + 1e-16f) + g_rskip[r * 64 + h];
    }
    __syncthreads();
    {
        float acc = 0.f;
#pragma unroll 8
        for (int h = 0; h < 64; h++) acc += remb_s[h] * W1[(64 + h) * 128 + tid];
        g_R[r * 128 + tid] = acc;
    }
    if (tid < 64) {
        float acc = 0.f;
#pragma unroll 8
        for (int h = 0; h < 64; h++) acc += Wp[tid * 64 + h] * remb_s[h];
        g_Wpre[r * 64 + tid] = acc;
    }
    if (tid == 0) {
        float acc = 0.f;
        for (int h = 0; h < 64; h++) acc += bp[h] * remb_s[h];
        g_c2[r] = acc;
    }
}

// ---------------- final per-edge scoring: one warp per edge ----------------
__global__ void __launch_bounds__(256) k_edge(
    const float* __restrict__ xo, const int* __restrict__ oidx,
    const int* __restrict__ ridx, const float* __restrict__ W2,
    const float* __restrict__ b2, float* __restrict__ out, int E) {
    __shared__ float W2s[128], cs[128];
    int tid = threadIdx.x;
    if (tid < 128) { W2s[tid] = W2[tid]; cs[tid] = g_cvec[tid]; }
    __syncthreads();
    int warp = tid >> 5, lane = tid & 31;
    float4 w4 = ((const float4*)W2s)[lane];
    float4 c4 = ((const float4*)cs)[lane];
    float b2v = __ldg(b2);
    int base = (blockIdx.x * 8 + warp) * 4;
#pragma unroll
    for (int i = 0; i < 4; i++) {
        int e = base + i;
        if (e >= E) return;
        int o = oidx[e];
        int r = ridx[e];
        float2 x2 = ((const float2*)xo)[(long long)o * 32 + lane];
        float2 p2 = ((const float2*)g_Wpre)[r * 32 + lane];
        float4 O4 = ((const float4*)g_O)[(long long)o * 32 + lane];
        float4 R4 = ((const float4*)g_R)[r * 32 + lane];
        float part = 0.125f * (x2.x * p2.x + x2.y * p2.y);
        float t;
        t = O4.x + R4.x + c4.x; part += fmaxf(t, 0.f) * w4.x;
        t = O4.y + R4.y + c4.y; part += fmaxf(t, 0.f) * w4.y;
        t = O4.z + R4.z + c4.z; part += fmaxf(t, 0.f) * w4.z;
        t = O4.w + R4.w + c4.w; part += fmaxf(t, 0.f) * w4.w;
        part += __shfl_xor_sync(0xffffffffu, part, 16);
        part += __shfl_xor_sync(0xffffffffu, part, 8);
        part += __shfl_xor_sync(0xffffffffu, part, 4);
        part += __shfl_xor_sync(0xffffffffu, part, 2);
        part += __shfl_xor_sync(0xffffffffu, part, 1);
        if (lane == 0) {
            float v = part + 0.125f * g_c2[r] + b2v;
            out[e] = fminf(fmaxf(v, -10.f), 10.f);
        }
    }
}

// ---------------- launch ----------------
extern "C" void kernel_launch(void* const* d_in, const int* in_sizes, int n_in,
                              void* d_out, int out_size) {
    const float* xo   = (const float*)d_in[0];
    const float* xr   = (const float*)d_in[1];
    const float* eat  = (const float*)d_in[2];
    const int*   oidx = (const int*)d_in[3];
    const int*   ridx = (const int*)d_in[4];
    const float* omg  = (const float*)d_in[5];
    const float* Wk   = (const float*)d_in[6];
    const float* bk   = (const float*)d_in[7];
    const float* Wq   = (const float*)d_in[8];
    const float* bq   = (const float*)d_in[9];
    const float* Wv   = (const float*)d_in[10];
    const float* bv   = (const float*)d_in[11];
    const float* We   = (const float*)d_in[12];
    const float* Wsk  = (const float*)d_in[13];
    const float* bsk  = (const float*)d_in[14];
    const float* Wp   = (const float*)d_in[15];
    const float* bp   = (const float*)d_in[16];
    const float* W1   = (const float*)d_in[17];
    const float* b1   = (const float*)d_in[18];
    const float* W2   = (const float*)d_in[19];
    const float* b2   = (const float*)d_in[20];
    float* out = (float*)d_out;
    int NOv = in_sizes[0] / 64;
    int NRv = in_sizes[1] / 32;
    int E   = in_sizes[3];

    const int kO_smem = (128 * 68 + 64 * 128) * 4;  // 67584 B
    cudaFuncSetAttribute(k_O, cudaFuncAttributeMaxDynamicSharedMemorySize, kO_smem);

    k_rider_pre<<<NRv, 64>>>(xr, Wq, bq, Wk, bk, We, Wsk, bsk);
    k_const<<<1, 128>>>(omg, W1, b1, bp);
    k_wc<<<64, 128>>>(Wp, W1);
    k_zero<<<1, 1024>>>(NRv);
    k_hist<<<256, 256>>>(ridx, E, NRv);
    k_scan<<<1, 1024>>>(NRv);
    k_scatter<<<512, 256>>>(ridx, E);
    k_O<<<(NOv + 127) / 128, dim3(16, 16), kO_smem>>>(xo, NOv);
    k_att<<<NRv, 128>>>(xo, eat, oidx, Wv, bv, We, Wp, bp, W1);
    k_edge<<<(E + 31) / 32, 256>>>(xo, oidx, ridx, W2, b2, out, E);
}

// round 2
// speedup vs baseline: 1.4266x; 1.4266x over previous
#include <cuda_runtime.h>
#include <cuda_fp16.h>

#define NO_MAX 100000
#define NR_MAX 1000
#define E_MAX  1000000

// ---------------- scratch (device globals; no allocations) ----------------
__device__ float g_A[NR_MAX * 64];      // Wk @ q_r
__device__ float g_c1[NR_MAX];          // q_r . bk
__device__ float g_qWe[NR_MAX * 4];     // We @ q_r
__device__ float g_rskip[NR_MAX * 64];  // x_rider@Wskip + bskip
__device__ float g_Wc[64 * 128];        // Wp @ W1[0:64]
__device__ float g_cvec[128];           // omega@W1c + b1 + bp@W1a
__device__ int   g_counts[NR_MAX];
__device__ int   g_starts[NR_MAX];
__device__ int   g_cursor[NR_MAX];
__device__ __align__(16) int    g_so[E_MAX];     // sorted order idx
__device__ __align__(16) float4 g_sea[E_MAX];    // sorted edge_attr
__device__ __align__(16) __half g_Oh[(long long)NO_MAX * 128];  // 25.6 MB fp16
__device__ __align__(16) __half g_xoh[(long long)NO_MAX * 64];  // 12.8 MB fp16 x_order
__device__ __align__(16) __half g_Rch[NR_MAX * 128];  // rider_emb@W1b + cvec (fp16)
__device__ float g_Wpre[NR_MAX * 64];   // Wp @ rider_emb
__device__ float g_c2[NR_MAX];          // bp . rider_emb

// ---------------- per-rider precompute ----------------
__global__ void k_rider_pre(const float* __restrict__ xr,
                            const float* __restrict__ Wq, const float* __restrict__ bq,
                            const float* __restrict__ Wk, const float* __restrict__ bk,
                            const float* __restrict__ We,
                            const float* __restrict__ Wsk, const float* __restrict__ bsk) {
    int r = blockIdx.x, h = threadIdx.x;  // 64 threads
    __shared__ float xs[32], qs[64];
    if (h < 32) xs[h] = xr[r * 32 + h];
    __syncthreads();
    float q = bq[h];
#pragma unroll 8
    for (int d = 0; d < 32; d++) q += xs[d] * Wq[d * 64 + h];
    qs[h] = q;
    float sk = bsk[h];
#pragma unroll 8
    for (int d = 0; d < 32; d++) sk += xs[d] * Wsk[d * 64 + h];
    g_rskip[r * 64 + h] = sk;
    __syncthreads();
    float a = 0.f;
#pragma unroll 8
    for (int t = 0; t < 64; t++) a += Wk[h * 64 + t] * qs[t];
    g_A[r * 64 + h] = a;
    if (h < 4) {
        float w = 0.f;
        for (int t = 0; t < 64; t++) w += We[h * 64 + t] * qs[t];
        g_qWe[r * 4 + h] = w;
    }
    if (h == 0) {
        float c = 0.f;
        for (int t = 0; t < 64; t++) c += bk[t] * qs[t];
        g_c1[r] = c;
    }
}

__global__ void k_const(const float* __restrict__ omg, const float* __restrict__ W1,
                        const float* __restrict__ b1, const float* __restrict__ bp) {
    int j = threadIdx.x;  // 128
    float c = b1[j];
    for (int m = 0; m < 32; m++) c += omg[m] * W1[(128 + m) * 128 + j];
    for (int d = 0; d < 64; d++) c += bp[d] * W1[d * 128 + j];
    g_cvec[j] = c;
}

__global__ void k_wc(const float* __restrict__ Wp, const float* __restrict__ W1) {
    __shared__ float wp[64];
    int d = blockIdx.x, j = threadIdx.x;  // 64 blocks x 128 threads
    if (j < 64) wp[j] = Wp[d * 64 + j];
    __syncthreads();
    float acc = 0.f;
#pragma unroll 8
    for (int t = 0; t < 64; t++) acc += wp[t] * W1[t * 128 + j];
    g_Wc[d * 128 + j] = acc;
}

// ---------------- bucket edges by rider (counting sort) ----------------
__global__ void k_zero(int NRv) {
    int t = threadIdx.x;
    if (t < NRv) g_counts[t] = 0;
}

__global__ void k_hist(const int* __restrict__ ridx, int E, int NRv) {
    __shared__ int sh[NR_MAX];
    int tid = threadIdx.x;
    for (int i = tid; i < NRv; i += blockDim.x) sh[i] = 0;
    __syncthreads();
    for (int e = blockIdx.x * blockDim.x + tid; e < E; e += gridDim.x * blockDim.x)
        atomicAdd(&sh[ridx[e]], 1);
    __syncthreads();
    for (int i = tid; i < NRv; i += blockDim.x) {
        int c = sh[i];
        if (c) atomicAdd(&g_counts[i], c);
    }
}

__global__ void k_scan(int NRv) {
    __shared__ int s[1024];
    int t = threadIdx.x;
    int v = (t < NRv) ? g_counts[t] : 0;
    s[t] = v;
    __syncthreads();
    for (int off = 1; off < 1024; off <<= 1) {
        int u = (t >= off) ? s[t - off] : 0;
        __syncthreads();
        s[t] += u;
        __syncthreads();
    }
    if (t < NRv) {
        int st = s[t] - v;
        g_starts[t] = st;
        g_cursor[t] = st;
    }
}

// scatter sorted records: (order idx, edge_attr) per bucketed position
__global__ void k_scatter(const int* __restrict__ ridx, const int* __restrict__ oidx,
                          const float* __restrict__ eat, int E) {
    for (int e = blockIdx.x * blockDim.x + threadIdx.x; e < E; e += gridDim.x * blockDim.x) {
        int r = ridx[e];
        int pos = atomicAdd(&g_cursor[r], 1);
        g_so[pos] = oidx[e];
        g_sea[pos] = ((const float4*)eat)[e];
    }
}

// ---------------- O = x_order @ Wc -> fp16; also pack x_order -> fp16 ----------------
__global__ void __launch_bounds__(256) k_O(const float* __restrict__ xo, int NOv) {
    extern __shared__ float dsm[];
    float* Xs  = dsm;             // [128][68]
    float* Wcs = dsm + 128 * 68;  // [64][128]
    int tx = threadIdx.x, ty = threadIdx.y;  // 16x16
    int tid = ty * 16 + tx;
    int row0 = blockIdx.x * 128;
    for (int i = tid; i < 64 * 32; i += 256)
        ((float4*)Wcs)[i] = ((const float4*)g_Wc)[i];
    for (int i = tid; i < 128 * 16; i += 256) {
        int row = i >> 4, kq = i & 15;
        float4 xv = make_float4(0.f, 0.f, 0.f, 0.f);
        int gr = row0 + row;
        if (gr < NOv) xv = ((const float4*)xo)[gr * 16 + kq];
        *((float4*)(Xs + row * 68 + kq * 4)) = xv;
    }
    __syncthreads();
    // emit fp16 copy of x_order
    for (int i = tid; i < 128 * 32; i += 256) {
        int row = i >> 5, c = i & 31;
        int gr = row0 + row;
        if (gr < NOv) {
            float a = Xs[row * 68 + 2 * c], b = Xs[row * 68 + 2 * c + 1];
            ((half2*)g_xoh)[(long long)gr * 32 + c] = __floats2half2_rn(a, b);
        }
    }
    float acc[8][8];
#pragma unroll
    for (int i = 0; i < 8; i++)
#pragma unroll
        for (int j = 0; j < 8; j++) acc[i][j] = 0.f;
#pragma unroll 8
    for (int k = 0; k < 64; k++) {
        float a[8];
#pragma unroll
        for (int i = 0; i < 8; i++) a[i] = Xs[(ty * 8 + i) * 68 + k];
        float4 b0 = *((const float4*)(Wcs + k * 128 + tx * 4));
        float4 b1 = *((const float4*)(Wcs + k * 128 + 64 + tx * 4));
#pragma unroll
        for (int i = 0; i < 8; i++) {
            acc[i][0] += a[i] * b0.x; acc[i][1] += a[i] * b0.y;
            acc[i][2] += a[i] * b0.z; acc[i][3] += a[i] * b0.w;
            acc[i][4] += a[i] * b1.x; acc[i][5] += a[i] * b1.y;
            acc[i][6] += a[i] * b1.z; acc[i][7] += a[i] * b1.w;
        }
    }
#pragma unroll
    for (int i = 0; i < 8; i++) {
        int gr = row0 + ty * 8 + i;
        if (gr < NOv) {
            half2* dst = (half2*)g_Oh + (long long)gr * 64;
            dst[tx * 2]          = __floats2half2_rn(acc[i][0], acc[i][1]);
            dst[tx * 2 + 1]      = __floats2half2_rn(acc[i][2], acc[i][3]);
            dst[32 + tx * 2]     = __floats2half2_rn(acc[i][4], acc[i][5]);
            dst[32 + tx * 2 + 1] = __floats2half2_rn(acc[i][6], acc[i][7]);
        }
    }
}

// ---------------- attention: warp-cooperative, 2-reg accumulator per lane ----------------
__global__ void __launch_bounds__(256) k_att(
    const float* __restrict__ xo,
    const float* __restrict__ Wv, const float* __restrict__ bv,
    const float* __restrict__ We, const float* __restrict__ Wp,
    const float* __restrict__ bp, const float* __restrict__ W1) {
    int r = blockIdx.x, tid = threadIdx.x;
    int lane = tid & 31, warp = tid >> 5;
    __shared__ float As[64], qWes[4], c1s;
    __shared__ float wsum[8][64];
    __shared__ float wsc[8][5];
    __shared__ float xs_s[64], remb_s[64], eas[4], asum_s;
    if (tid < 64) As[tid] = g_A[r * 64 + tid];
    if (tid < 4)  qWes[tid] = g_qWe[r * 4 + tid];
    if (tid == 0) c1s = g_c1[r];
    __syncthreads();
    float a0 = As[lane], a1 = As[lane + 32];
    float q0 = qWes[0], q1 = qWes[1], q2 = qWes[2], q3 = qWes[3], c1 = c1s;
    int start = g_starts[r], cnt = g_counts[r];

    float xs0 = 0.f, xs1 = 0.f;
    float asum = 0.f, e0 = 0.f, e1 = 0.f, e2 = 0.f, e3 = 0.f;
    for (int i = warp; i < cnt; i += 8) {
        int idx = start + i;
        int o = __ldg(g_so + idx);             // broadcast
        float4 ea = __ldg(g_sea + idx);        // broadcast
        const float* xp = xo + (long long)o * 64;
        float x0 = __ldg(xp + lane);
        float x1 = __ldg(xp + lane + 32);
        float pd = x0 * a0 + x1 * a1;
        pd += __shfl_xor_sync(0xffffffffu, pd, 16);
        pd += __shfl_xor_sync(0xffffffffu, pd, 8);
        pd += __shfl_xor_sync(0xffffffffu, pd, 4);
        pd += __shfl_xor_sync(0xffffffffu, pd, 2);
        pd += __shfl_xor_sync(0xffffffffu, pd, 1);
        float dot = pd + c1 + ea.x * q0 + ea.y * q1 + ea.z * q2 + ea.w * q3;
        float w = __expf(0.125f * dot);  // softmax shift-invariance: no max needed
        asum += w;
        e0 += w * ea.x; e1 += w * ea.y; e2 += w * ea.z; e3 += w * ea.w;
        xs0 += w * x0; xs1 += w * x1;
    }
    wsum[warp][lane] = xs0;
    wsum[warp][lane + 32] = xs1;
    if (lane == 0) {
        wsc[warp][0] = asum; wsc[warp][1] = e0; wsc[warp][2] = e1;
        wsc[warp][3] = e2;   wsc[warp][4] = e3;
    }
    __syncthreads();
    if (tid < 64) {
        float v = 0.f;
#pragma unroll
        for (int w = 0; w < 8; w++) v += wsum[w][tid];
        xs_s[tid] = v;
    }
    if (tid < 5) {
        float v = 0.f;
#pragma unroll
        for (int w = 0; w < 8; w++) v += wsc[w][tid];
        if (tid == 0) asum_s = v; else eas[tid - 1] = v;
    }
    __syncthreads();
    if (tid < 64) {
        int h = tid;
        float t = asum_s * bv[h];
#pragma unroll 8
        for (int d = 0; d < 64; d++) t += xs_s[d] * Wv[d * 64 + h];
        t += eas[0] * We[h] + eas[1] * We[64 + h] + eas[2] * We[128 + h] + eas[3] * We[192 + h];
        remb_s[h] = t / (asum_s + 1e-16f) + g_rskip[r * 64 + h];
    }
    __syncthreads();
    if (tid < 128) {
        float acc = g_cvec[tid];
#pragma unroll 8
        for (int h = 0; h < 64; h++) acc += remb_s[h] * W1[(64 + h) * 128 + tid];
        g_Rch[r * 128 + tid] = __float2half(acc);
    }
    if (tid < 64) {
        float acc = 0.f;
#pragma unroll 8
        for (int h = 0; h < 64; h++) acc += Wp[tid * 64 + h] * remb_s[h];
        g_Wpre[r * 64 + tid] = acc;
    }
    if (tid == 0) {
        float acc = 0.f;
        for (int h = 0; h < 64; h++) acc += bp[h] * remb_s[h];
        g_c2[r] = acc;
    }
}

// ---------------- final per-edge scoring: warp per edge, fp16 activations ----------------
__global__ void __launch_bounds__(256) k_edge(
    const int* __restrict__ oidx, const int* __restrict__ ridx,
    const float* __restrict__ W2, const float* __restrict__ b2,
    float* __restrict__ out, int E) {
    __shared__ float W2s[128];
    int tid = threadIdx.x;
    if (tid < 128) W2s[tid] = W2[tid];
    __syncthreads();
    int warp = tid >> 5, lane = tid & 31;
    float4 w4 = ((const float4*)W2s)[lane];
    float b2v = __ldg(b2);
    int base = (blockIdx.x * 8 + warp) * 4;
#pragma unroll
    for (int i = 0; i < 4; i++) {
        int e = base + i;
        if (e >= E) return;
        int o = __ldg(oidx + e);
        int r = __ldg(ridx + e);
        uint2 Ou = ((const uint2*)g_Oh)[(long long)o * 32 + lane];   // 4 halves: dims 4l..4l+3
        uint2 Ru = ((const uint2*)g_Rch)[r * 32 + lane];
        unsigned xu = ((const unsigned*)g_xoh)[(long long)o * 32 + lane];  // 2 halves
        float2 p2 = ((const float2*)g_Wpre)[r * 32 + lane];
        float2 oA = __half22float2(*(const half2*)&Ou.x);
        float2 oB = __half22float2(*(const half2*)&Ou.y);
        float2 rA = __half22float2(*(const half2*)&Ru.x);
        float2 rB = __half22float2(*(const half2*)&Ru.y);
        float2 xf = __half22float2(*(const half2*)&xu);
        float part = 0.125f * (xf.x * p2.x + xf.y * p2.y);
        part += fmaxf(oA.x + rA.x, 0.f) * w4.x;
        part += fmaxf(oA.y + rA.y, 0.f) * w4.y;
        part += fmaxf(oB.x + rB.x, 0.f) * w4.z;
        part += fmaxf(oB.y + rB.y, 0.f) * w4.w;
        part += __shfl_xor_sync(0xffffffffu, part, 16);
        part += __shfl_xor_sync(0xffffffffu, part, 8);
        part += __shfl_xor_sync(0xffffffffu, part, 4);
        part += __shfl_xor_sync(0xffffffffu, part, 2);
        part += __shfl_xor_sync(0xffffffffu, part, 1);
        if (lane == 0) {
            float v = part + 0.125f * __ldg(g_c2 + r) + b2v;
            out[e] = fminf(fmaxf(v, -10.f), 10.f);
        }
    }
}

// ---------------- launch ----------------
extern "C" void kernel_launch(void* const* d_in, const int* in_sizes, int n_in,
                              void* d_out, int out_size) {
    const float* xo   = (const float*)d_in[0];
    const float* xr   = (const float*)d_in[1];
    const float* eat  = (const float*)d_in[2];
    const int*   oidx = (const int*)d_in[3];
    const int*   ridx = (const int*)d_in[4];
    const float* omg  = (const float*)d_in[5];
    const float* Wk   = (const float*)d_in[6];
    const float* bk   = (const float*)d_in[7];
    const float* Wq   = (const float*)d_in[8];
    const float* bq   = (const float*)d_in[9];
    const float* Wv   = (const float*)d_in[10];
    const float* bv   = (const float*)d_in[11];
    const float* We   = (const float*)d_in[12];
    const float* Wsk  = (const float*)d_in[13];
    const float* bsk  = (const float*)d_in[14];
    const float* Wp   = (const float*)d_in[15];
    const float* bp   = (const float*)d_in[16];
    const float* W1   = (const float*)d_in[17];
    const float* b1   = (const float*)d_in[18];
    const float* W2   = (const float*)d_in[19];
    const float* b2   = (const float*)d_in[20];
    float* out = (float*)d_out;
    int NOv = in_sizes[0] / 64;
    int NRv = in_sizes[1] / 32;
    int E   = in_sizes[3];

    const int kO_smem = (128 * 68 + 64 * 128) * 4;  // 67584 B
    cudaFuncSetAttribute(k_O, cudaFuncAttributeMaxDynamicSharedMemorySize, kO_smem);

    k_rider_pre<<<NRv, 64>>>(xr, Wq, bq, Wk, bk, We, Wsk, bsk);
    k_const<<<1, 128>>>(omg, W1, b1, bp);
    k_wc<<<64, 128>>>(Wp, W1);
    k_zero<<<1, 1024>>>(NRv);
    k_hist<<<256, 256>>>(ridx, E, NRv);
    k_scan<<<1, 1024>>>(NRv);
    k_scatter<<<512, 256>>>(ridx, oidx, eat, E);
    k_O<<<(NOv + 127) / 128, dim3(16, 16), kO_smem>>>(xo, NOv);
    k_att<<<NRv, 256>>>(xo, Wv, bv, We, Wp, bp, W1);
    k_edge<<<(E + 31) / 32, 256>>>(oidx, ridx, W2, b2, out, E);
}